// round 16
// baseline (speedup 1.0000x reference)
#include <cuda_runtime.h>
#include <cuda_bf16.h>
#include <cuda_fp16.h>
#include <math.h>
#include <stdint.h>

#define BB 4
#define LL 256
#define DD 768
#define HH 12
#define NSTEPS 6
#define NROW 1024
#define CC 50257
#define QKVLD 2304
#define KDIM 768
#define CSP (NROW*DD)

#define OFF_IPW 0
#define OFF_AOW (2304*768)
#define OFF_W1  ((2304+768)*768)
#define OFF_W2  ((2304+2*768)*768)
#define WS_TOT  ((2304+3*768)*768)

// ---------------- scratch ----------------
__device__ float g_hbuf[(size_t)NROW*7*DD];
__device__ float g_qkvc[(size_t)NROW*6*QKVLD];
__device__ float g_attno[(size_t)NROW*DD];
__device__ float g_pp [(size_t)2*CSP];
__device__ float g_ffp[(size_t)2*CSP];
__device__ float g_y  [(size_t)NROW*DD];
__device__ __half g_hwh[(size_t)CC*DD];          // head W fp16
__device__ __nv_bfloat16 g_wsh[(size_t)WS_TOT];  // small weights hi
__device__ __nv_bfloat16 g_wsl[(size_t)WS_TOT];  // small weights lo

// ---------------- helpers ----------------
__device__ __forceinline__ uint32_t s2u(const void* p){
  uint32_t a; asm("{ .reg .u64 t; cvta.to.shared.u64 t, %1; cvt.u32.u64 %0, t; }"
                  : "=r"(a) : "l"(p)); return a;
}
__device__ __forceinline__ void ldsm4(uint32_t* r, uint32_t addr){
  asm volatile("ldmatrix.sync.aligned.m8n8.x4.shared.b16 {%0,%1,%2,%3}, [%4];"
    : "=r"(r[0]),"=r"(r[1]),"=r"(r[2]),"=r"(r[3]) : "r"(addr));
}
__device__ __forceinline__ void mma16816(float* c, const uint32_t* a, const uint32_t* b){
  asm volatile("mma.sync.aligned.m16n8k16.row.col.f32.bf16.bf16.f32 "
    "{%0,%1,%2,%3}, {%4,%5,%6,%7}, {%8,%9}, {%0,%1,%2,%3};"
    : "+f"(c[0]),"+f"(c[1]),"+f"(c[2]),"+f"(c[3])
    : "r"(a[0]),"r"(a[1]),"r"(a[2]),"r"(a[3]), "r"(b[0]),"r"(b[1]));
}
__device__ __forceinline__ void mma16816h(float* c, const uint32_t* a, const uint32_t* b){
  asm volatile("mma.sync.aligned.m16n8k16.row.col.f32.f16.f16.f32 "
    "{%0,%1,%2,%3}, {%4,%5,%6,%7}, {%8,%9}, {%0,%1,%2,%3};"
    : "+f"(c[0]),"+f"(c[1]),"+f"(c[2]),"+f"(c[3])
    : "r"(a[0]),"r"(a[1]),"r"(a[2]),"r"(a[3]), "r"(b[0]),"r"(b[1]));
}
__device__ __forceinline__ void split2(float a, float b, uint32_t& h, uint32_t& l){
  __nv_bfloat16 ha = __float2bfloat16(a), hb = __float2bfloat16(b);
  __nv_bfloat16 la = __float2bfloat16(a - __bfloat162float(ha));
  __nv_bfloat16 lb = __float2bfloat16(b - __bfloat162float(hb));
  uint16_t uha = *(uint16_t*)&ha, uhb = *(uint16_t*)&hb;
  uint16_t ula = *(uint16_t*)&la, ulb = *(uint16_t*)&lb;
  h = ((uint32_t)uhb << 16) | uha;
  l = ((uint32_t)ulb << 16) | ula;
}

// ---------------- weight conversions ----------------
__global__ void conv_w_kernel(const float* __restrict__ w,
                              __nv_bfloat16* __restrict__ h,
                              __nv_bfloat16* __restrict__ l, int n4)
{
  int i = blockIdx.x * 256 + threadIdx.x;
  if (i >= n4) return;
  float4 v = reinterpret_cast<const float4*>(w)[i];
  uint32_t h0,l0,h1,l1;
  split2(v.x, v.y, h0, l0);
  split2(v.z, v.w, h1, l1);
  *(uint2*)(h + (size_t)i*4) = make_uint2(h0, h1);
  *(uint2*)(l + (size_t)i*4) = make_uint2(l0, l1);
}
__global__ void conv_w16_kernel(const float* __restrict__ w,
                                __half* __restrict__ h, int n4)
{
  int i = blockIdx.x * 256 + threadIdx.x;
  if (i >= n4) return;
  float4 v = reinterpret_cast<const float4*>(w)[i];
  __half2 a = __floats2half2_rn(v.x, v.y);
  __half2 b = __floats2half2_rn(v.z, v.w);
  *(uint2*)(h + (size_t)i*4) = make_uint2(*(uint32_t*)&a, *(uint32_t*)&b);
}

// ---------------- elementwise ----------------
__global__ void embed_kernel(const int* __restrict__ x, const float* __restrict__ emb,
                             const float* __restrict__ pos, const float* __restrict__ te0) {
  int n = blockIdx.x;
  int l = n % LL;
  int tok = x[n];
  const float* e = emb + (size_t)tok * DD;
  const float* p = pos + (size_t)l * DD;
  float* dst = g_hbuf + (size_t)n * 7 * DD;
  for (int i = threadIdx.x; i < DD; i += blockDim.x) dst[i] = e[i] + p[i] + te0[i];
}

// ---------------- bf16 3-term GEMM (pre-split W), split-K capable ------------
template<int BM, int BN, int SPLITK>
__global__ __launch_bounds__((BM/64)*(BN/32)*32)
void gemm_mma_kernel(const float* __restrict__ A, int lda,
                     const float* __restrict__ A2,
                     const __nv_bfloat16* __restrict__ Wh,
                     const __nv_bfloat16* __restrict__ Wl,
                     const float* __restrict__ bias,
                     float* __restrict__ C, int ldc,
                     int N, int relu)
{
  constexpr int NWN = BN/32;
  constexpr int NTHR = (BM/64)*(BN/32)*32;
  constexpr int RPP = NTHR/8;
  constexpr int PA = BM/RPP, PB = BN/RPP;
  constexpr int ABYTES = BM*64, BBYTES = BN*64;
  constexpr int NIT = KDIM/32/SPLITK;

  extern __shared__ char smem[];
  const int OAh = 0, OAl = 2*ABYTES, OBh = 4*ABYTES, OBl = 4*ABYTES + 2*BBYTES;
  uint32_t sb = s2u(smem);

  int tid = threadIdx.x, lane = tid & 31, wid = tid >> 5;
  int wm = wid / NWN, wn = wid % NWN;
  int bm = blockIdx.x * BM, bn = blockIdx.y * BN;
  int kz = (SPLITK > 1) ? blockIdx.z : 0;
  int kbase = kz * (KDIM / SPLITK);
  int lr = tid >> 3, lq = tid & 7;

  float acc[4][4][4];
  #pragma unroll
  for (int i = 0; i < 4; i++)
    #pragma unroll
    for (int j = 0; j < 4; j++)
      #pragma unroll
      for (int q = 0; q < 4; q++) acc[i][j][q] = 0.f;

  float4 sa[PA];
  uint2 wh_[PB], wl_[PB];

  auto load_tiles = [&](int k0){
    #pragma unroll
    for (int p = 0; p < PA; p++) {
      size_t off = (size_t)(bm + p*RPP + lr) * lda + kbase + k0 + lq*4;
      sa[p] = *(const float4*)(A + off);
      if (A2) {
        float4 b2 = *(const float4*)(A2 + off);
        sa[p].x = fmaxf(sa[p].x + b2.x, 0.f);
        sa[p].y = fmaxf(sa[p].y + b2.y, 0.f);
        sa[p].z = fmaxf(sa[p].z + b2.z, 0.f);
        sa[p].w = fmaxf(sa[p].w + b2.w, 0.f);
      }
    }
    #pragma unroll
    for (int p = 0; p < PB; p++) {
      int wr = bn + p*RPP + lr;
      size_t off = (size_t)wr * KDIM + kbase + k0 + lq*4;
      wh_[p] = *(const uint2*)(Wh + off);
      wl_[p] = *(const uint2*)(Wl + off);
    }
  };
  auto store_tiles = [&](int b){
    #pragma unroll
    for (int p = 0; p < PA; p++) {
      int r = p*RPP + lr;
      int byte = r*64 + ((((lq>>1) ^ ((r>>1)&3))<<4) | ((lq&1)<<3));
      uint32_t h0,l0,h1,l1;
      split2(sa[p].x, sa[p].y, h0, l0);
      split2(sa[p].z, sa[p].w, h1, l1);
      *(uint2*)(smem + OAh + b*ABYTES + byte) = make_uint2(h0,h1);
      *(uint2*)(smem + OAl + b*ABYTES + byte) = make_uint2(l0,l1);
    }
    #pragma unroll
    for (int p = 0; p < PB; p++) {
      int r = p*RPP + lr;
      int byte = r*64 + ((((lq>>1) ^ ((r>>1)&3))<<4) | ((lq&1)<<3));
      *(uint2*)(smem + OBh + b*BBYTES + byte) = wh_[p];
      *(uint2*)(smem + OBl + b*BBYTES + byte) = wl_[p];
    }
  };

  load_tiles(0);
  store_tiles(0);
  __syncthreads();

  int buf = 0;
  for (int it = 0; it < NIT; it++) {
    bool more = (it < NIT-1);
    if (more) load_tiles((it+1)*32);

    #pragma unroll
    for (int ks = 0; ks < 2; ks++) {
      uint32_t ah[4][4], al[4][4], bh[4][2], bl[4][2];
      #pragma unroll
      for (int mi = 0; mi < 4; mi++) {
        int r = wm*64 + mi*16 + (lane & 15);
        int kc = ks*2 + (lane >> 4);
        uint32_t byte = r*64 + ((kc ^ ((r>>1)&3))<<4);
        ldsm4(ah[mi], sb + OAh + buf*ABYTES + byte);
        ldsm4(al[mi], sb + OAl + buf*ABYTES + byte);
      }
      #pragma unroll
      for (int np = 0; np < 2; np++) {
        int r = wn*32 + np*16 + (lane & 7) + ((lane>>4)&1)*8;
        int kc = ks*2 + ((lane>>3)&1);
        uint32_t byte = r*64 + ((kc ^ ((r>>1)&3))<<4);
        uint32_t t4[4];
        ldsm4(t4, sb + OBh + buf*BBYTES + byte);
        bh[np*2][0]=t4[0]; bh[np*2][1]=t4[1]; bh[np*2+1][0]=t4[2]; bh[np*2+1][1]=t4[3];
        ldsm4(t4, sb + OBl + buf*BBYTES + byte);
        bl[np*2][0]=t4[0]; bl[np*2][1]=t4[1]; bl[np*2+1][0]=t4[2]; bl[np*2+1][1]=t4[3];
      }
      #pragma unroll
      for (int mi = 0; mi < 4; mi++)
        #pragma unroll
        for (int ni = 0; ni < 4; ni++) {
          mma16816(acc[mi][ni], ah[mi], bh[ni]);
          mma16816(acc[mi][ni], ah[mi], bl[ni]);
          mma16816(acc[mi][ni], al[mi], bh[ni]);
        }
    }
    if (more) {
      store_tiles(buf ^ 1);
      __syncthreads();
      buf ^= 1;
    }
  }

  float* Cz = C + (size_t)kz * CSP;
  bool addb = (kz == 0);
  #pragma unroll
  for (int mi = 0; mi < 4; mi++) {
    int r0 = bm + wm*64 + mi*16 + (lane >> 2);
    #pragma unroll
    for (int ni = 0; ni < 4; ni++) {
      int c0 = bn + wn*32 + ni*8 + ((lane & 3) << 1);
      float* p0 = Cz + (size_t)r0 * ldc;
      float* p1 = Cz + (size_t)(r0 + 8) * ldc;
      float bv0 = addb ? __ldg(bias + c0) : 0.f;
      float bv1 = addb ? __ldg(bias + c0 + 1) : 0.f;
      float v0 = acc[mi][ni][0] + bv0, v1 = acc[mi][ni][1] + bv1;
      float v2 = acc[mi][ni][2] + bv0, v3 = acc[mi][ni][3] + bv1;
      if (relu) {
        v0 = fmaxf(v0, 0.f); v1 = fmaxf(v1, 0.f);
        v2 = fmaxf(v2, 0.f); v3 = fmaxf(v3, 0.f);
      }
      p0[c0] = v0; p0[c0+1] = v1; p1[c0] = v2; p1[c0+1] = v3;
    }
  }
}

// ---------------- fp16 1-term head GEMM ----------------
#define HEAD_SMEM (4*128*64)
__global__ __launch_bounds__(256)
void gemm_head_kernel(const float* __restrict__ A, int lda,
                      const __half* __restrict__ Wh,
                      const float* __restrict__ bias,
                      float* __restrict__ C)
{
  constexpr int BM = 128, BN = 128;
  constexpr int ABYTES = BM*64, BBYTES = BN*64;
  constexpr int NIT = KDIM/32;

  extern __shared__ char smem[];
  const int OAh = 0, OBh = 2*ABYTES;
  uint32_t sb = s2u(smem);

  int tid = threadIdx.x, lane = tid & 31, wid = tid >> 5;
  int wm = wid >> 2, wn = wid & 3;
  int bm = blockIdx.x * BM, bn = blockIdx.y * BN;
  int lr = tid >> 3, lq = tid & 7;

  float acc[4][4][4];
  #pragma unroll
  for (int i = 0; i < 4; i++)
    #pragma unroll
    for (int j = 0; j < 4; j++)
      #pragma unroll
      for (int q = 0; q < 4; q++) acc[i][j][q] = 0.f;

  float4 sa[4];
  uint2 wv[4];

  auto load_tiles = [&](int k0){
    #pragma unroll
    for (int p = 0; p < 4; p++)
      sa[p] = *(const float4*)(A + (size_t)(bm + p*32 + lr) * lda + k0 + lq*4);
    #pragma unroll
    for (int p = 0; p < 4; p++) {
      int wr = bn + p*32 + lr;
      wv[p] = (wr < CC) ? *(const uint2*)(Wh + (size_t)wr * KDIM + k0 + lq*4)
                        : make_uint2(0,0);
    }
  };
  auto store_tiles = [&](int b){
    #pragma unroll
    for (int p = 0; p < 4; p++) {
      int r = p*32 + lr;
      int byte = r*64 + ((((lq>>1) ^ ((r>>1)&3))<<4) | ((lq&1)<<3));
      __half2 h0 = __floats2half2_rn(sa[p].x, sa[p].y);
      __half2 h1 = __floats2half2_rn(sa[p].z, sa[p].w);
      *(uint2*)(smem + OAh + b*ABYTES + byte) =
          make_uint2(*(uint32_t*)&h0, *(uint32_t*)&h1);
    }
    #pragma unroll
    for (int p = 0; p < 4; p++) {
      int r = p*32 + lr;
      int byte = r*64 + ((((lq>>1) ^ ((r>>1)&3))<<4) | ((lq&1)<<3));
      *(uint2*)(smem + OBh + b*BBYTES + byte) = wv[p];
    }
  };

  load_tiles(0);
  store_tiles(0);
  __syncthreads();

  int buf = 0;
  for (int it = 0; it < NIT; it++) {
    bool more = (it < NIT-1);
    if (more) load_tiles((it+1)*32);

    #pragma unroll
    for (int ks = 0; ks < 2; ks++) {
      uint32_t ah[4][4], bh[4][2];
      #pragma unroll
      for (int mi = 0; mi < 4; mi++) {
        int r = wm*64 + mi*16 + (lane & 15);
        int kc = ks*2 + (lane >> 4);
        uint32_t byte = r*64 + ((kc ^ ((r>>1)&3))<<4);
        ldsm4(ah[mi], sb + OAh + buf*ABYTES + byte);
      }
      #pragma unroll
      for (int np = 0; np < 2; np++) {
        int r = wn*32 + np*16 + (lane & 7) + ((lane>>4)&1)*8;
        int kc = ks*2 + ((lane>>3)&1);
        uint32_t byte = r*64 + ((kc ^ ((r>>1)&3))<<4);
        uint32_t t4[4];
        ldsm4(t4, sb + OBh + buf*BBYTES + byte);
        bh[np*2][0]=t4[0]; bh[np*2][1]=t4[1]; bh[np*2+1][0]=t4[2]; bh[np*2+1][1]=t4[3];
      }
      #pragma unroll
      for (int mi = 0; mi < 4; mi++)
        #pragma unroll
        for (int ni = 0; ni < 4; ni++)
          mma16816h(acc[mi][ni], ah[mi], bh[ni]);
    }
    if (more) {
      store_tiles(buf ^ 1);
      __syncthreads();
      buf ^= 1;
    }
  }

  #pragma unroll
  for (int mi = 0; mi < 4; mi++) {
    int r0 = bm + wm*64 + mi*16 + (lane >> 2);
    #pragma unroll
    for (int ni = 0; ni < 4; ni++) {
      int c0 = bn + wn*32 + ni*8 + ((lane & 3) << 1);
      float* p0 = C + (size_t)r0 * CC;
      float* p1 = C + (size_t)(r0 + 8) * CC;
      if (c0 < CC) {
        float bv = __ldg(bias + c0);
        p0[c0] = acc[mi][ni][0] + bv;
        p1[c0] = acc[mi][ni][2] + bv;
      }
      if (c0 + 1 < CC) {
        float bv = __ldg(bias + c0 + 1);
        p0[c0+1] = acc[mi][ni][1] + bv;
        p1[c0+1] = acc[mi][ni][3] + bv;
      }
    }
  }
}

// ---------------- flash attention, MLP-4 pipelined V loop ----------------
#define ATTN_SMEM ((64*36 + 64*132 + 32*132)*4 + 256*4)
__global__ __launch_bounds__(256) void attn_kernel(const int* __restrict__ amask, int t)
{
  int qt = blockIdx.x, h = blockIdx.y, b = blockIdx.z;
  int tid = threadIdx.x, lane = tid & 31, w = tid >> 5;
  extern __shared__ float sm[];
  float* Qs = sm;
  float* Kt = Qs + 64*36;
  float* P  = Kt + 64*132;
  int*   mkk = (int*)(P + 32*132);

  int l0 = qt * 32;
  size_t cbase = (size_t)b * LL * 6 * QKVLD;
  const float* vbase = g_qkvc + cbase + 2*DD + h*64 + lane*2;

  if (tid < 256) mkk[tid] = amask[b*LL + tid];
  {
    int q = tid >> 3, e0 = (tid & 7) * 8;
    const float* qp = g_qkvc + ((size_t)((b*LL + l0 + q)*6 + (t-1)))*QKVLD + h*64 + e0;
    #pragma unroll
    for (int i = 0; i < 8; i++) Qs[(e0+i)*36 + q] = qp[i];
  }

  float m[4], lsum[4], oacc[4][2];
  #pragma unroll
  for (int i = 0; i < 4; i++) {
    m[i] = -1e30f; lsum[i] = 0.f; oacc[i][0] = 0.f; oacc[i][1] = 0.f;
  }

  #pragma unroll
  for (int kt = 0; kt < 2; kt++) {
    __syncthreads();
    {
      int k = tid >> 1, e0 = (tid & 1) * 32;
      const float* kp = g_qkvc + cbase + (size_t)(kt*128 + k)*6*QKVLD + DD + h*64 + e0;
      #pragma unroll
      for (int i = 0; i < 32; i++) Kt[(e0+i)*132 + k] = kp[i];
    }
    __syncthreads();

    float s[4][4];
    #pragma unroll
    for (int i = 0; i < 4; i++)
      #pragma unroll
      for (int j = 0; j < 4; j++) s[i][j] = 0.f;
    #pragma unroll 8
    for (int e = 0; e < 64; e++) {
      float4 qv = *(const float4*)&Qs[e*36 + w*4];
      float4 kv = *(const float4*)&Kt[e*132 + lane*4];
      s[0][0]+=qv.x*kv.x; s[0][1]+=qv.x*kv.y; s[0][2]+=qv.x*kv.z; s[0][3]+=qv.x*kv.w;
      s[1][0]+=qv.y*kv.x; s[1][1]+=qv.y*kv.y; s[1][2]+=qv.y*kv.z; s[1][3]+=qv.y*kv.w;
      s[2][0]+=qv.z*kv.x; s[2][1]+=qv.z*kv.y; s[2][2]+=qv.z*kv.z; s[2][3]+=qv.z*kv.w;
      s[3][0]+=qv.w*kv.x; s[3][1]+=qv.w*kv.y; s[3][2]+=qv.w*kv.z; s[3][3]+=qv.w*kv.w;
    }
    int j0 = kt*128 + lane*4;
    float msk[4];
    #pragma unroll
    for (int j = 0; j < 4; j++) msk[j] = mkk[j0+j] ? 0.f : -1e30f;
    #pragma unroll
    for (int i = 0; i < 4; i++) {
      #pragma unroll
      for (int j = 0; j < 4; j++) s[i][j] = s[i][j]*0.125f + msk[j];
      float mt = fmaxf(fmaxf(s[i][0], s[i][1]), fmaxf(s[i][2], s[i][3]));
      #pragma unroll
      for (int o = 16; o; o >>= 1) mt = fmaxf(mt, __shfl_xor_sync(0xffffffffu, mt, o));
      float mnew = fmaxf(m[i], mt);
      float ps = 0.f;
      #pragma unroll
      for (int j = 0; j < 4; j++) { s[i][j] = __expf(s[i][j] - mnew); ps += s[i][j]; }
      #pragma unroll
      for (int o = 16; o; o >>= 1) ps += __shfl_xor_sync(0xffffffffu, ps, o);
      float alpha = __expf(m[i] - mnew);
      lsum[i] = lsum[i]*alpha + ps;
      oacc[i][0] *= alpha; oacc[i][1] *= alpha;
      m[i] = mnew;
    }
    #pragma unroll
    for (int i = 0; i < 4; i++)
      *(float4*)&P[(w*4 + i)*132 + lane*4] = make_float4(s[i][0], s[i][1], s[i][2], s[i][3]);
    __syncwarp();

    // V: MLP-4 pipelined — 4 independent LDG.64 + 4 LDS.128 per group
    #pragma unroll 2
    for (int k0 = 0; k0 < 128; k0 += 4) {
      float2 v[4];
      #pragma unroll
      for (int u = 0; u < 4; u++)
        v[u] = *(const float2*)(vbase + (size_t)(kt*128 + k0 + u)*6*QKVLD);
      float4 pq[4];
      #pragma unroll
      for (int i = 0; i < 4; i++)
        pq[i] = *(const float4*)&P[(w*4 + i)*132 + k0];
      #pragma unroll
      for (int i = 0; i < 4; i++) {
        oacc[i][0] += pq[i].x*v[0].x + pq[i].y*v[1].x + pq[i].z*v[2].x + pq[i].w*v[3].x;
        oacc[i][1] += pq[i].x*v[0].y + pq[i].y*v[1].y + pq[i].z*v[2].y + pq[i].w*v[3].y;
      }
    }
  }

  for (int s = 1; s < t; s++) {
    #pragma unroll
    for (int i = 0; i < 4; i++) {
      int qloc = w*4 + i;
      int row = b*LL + l0 + qloc;
      const float* base = g_qkvc + ((size_t)(row*6 + s))*QKVLD;
      float2 kv = *(const float2*)(base + DD + h*64 + lane*2);
      float d = Qs[(2*lane)*36 + qloc]*kv.x + Qs[(2*lane+1)*36 + qloc]*kv.y;
      #pragma unroll
      for (int o = 16; o; o >>= 1) d += __shfl_xor_sync(0xffffffffu, d, o);
      d = (amask[row] != 0) ? d*0.125f : -1e30f;
      float mnew = fmaxf(m[i], d);
      float p = __expf(d - mnew);
      float alpha = __expf(m[i] - mnew);
      lsum[i] = lsum[i]*alpha + p;
      float2 v = *(const float2*)(base + 2*DD + h*64 + lane*2);
      oacc[i][0] = oacc[i][0]*alpha + p*v.x;
      oacc[i][1] = oacc[i][1]*alpha + p*v.y;
      m[i] = mnew;
    }
  }

  #pragma unroll
  for (int i = 0; i < 4; i++) {
    int qloc = w*4 + i;
    int row = b*LL + l0 + qloc;
    float iv = 1.f / lsum[i];
    *(float2*)(g_attno + (size_t)row*DD + h*64 + lane*2) =
        make_float2(oacc[i][0]*iv, oacc[i][1]*iv);
  }
}

// ---------------- fused (partial+partial)+residual + LayerNorm (+time emb) ----
__global__ void add_ln_kernel(const float* __restrict__ A, const float* __restrict__ A2,
                              int lda,
                              const float* __restrict__ R, int ldr,
                              const float* __restrict__ gma, const float* __restrict__ bta,
                              float* __restrict__ out, int ldo,
                              const float* __restrict__ tvec)
{
  int row = blockIdx.x;
  int tid = threadIdx.x;
  const float* pa = A + (size_t)row * lda;
  const float* pa2 = A2 + (size_t)row * lda;
  const float* pr = R + (size_t)row * ldr;
  float* po = out + (size_t)row * ldo;
  float v[3]; float s = 0.f, sq = 0.f;
  #pragma unroll
  for (int i = 0; i < 3; i++) {
    int idx = tid + i * 256;
    float xx = pa[idx] + pa2[idx] + pr[idx];
    v[i] = xx; s += xx; sq += xx * xx;
  }
  __shared__ float r1[8], r2[8];
  for (int o = 16; o; o >>= 1) {
    s  += __shfl_xor_sync(0xffffffffu, s, o);
    sq += __shfl_xor_sync(0xffffffffu, sq, o);
  }
  if ((tid & 31) == 0) { r1[tid >> 5] = s; r2[tid >> 5] = sq; }
  __syncthreads();
  s = 0.f; sq = 0.f;
  #pragma unroll
  for (int ww = 0; ww < 8; ww++) { s += r1[ww]; sq += r2[ww]; }
  float mean = s * (1.f / DD);
  float var  = sq * (1.f / DD) - mean * mean;
  float rinv = rsqrtf(var + 1e-5f);
  #pragma unroll
  for (int i = 0; i < 3; i++) {
    int idx = tid + i * 256;
    float o = (v[i] - mean) * rinv * gma[idx] + bta[idx];
    if (tvec) o += tvec[idx];
    po[idx] = o;
  }
}

// ---------------- host launch ----------------
extern "C" void kernel_launch(void* const* d_in, const int* in_sizes, int n_in,
                              void* d_out, int out_size)
{
  const int*   x     = (const int*)d_in[0];
  const int*   amask = (const int*)d_in[1];
  const float* emb   = (const float*)d_in[2];
  const float* pos   = (const float*)d_in[3];
  const float* temb  = (const float*)d_in[4];
  const float* ipw   = (const float*)d_in[5];
  const float* ipb   = (const float*)d_in[6];
  const float* aow   = (const float*)d_in[7];
  const float* aob   = (const float*)d_in[8];
  const float* ln1g  = (const float*)d_in[9];
  const float* ln1b  = (const float*)d_in[10];
  const float* w1    = (const float*)d_in[11];
  const float* b1    = (const float*)d_in[12];
  const float* w2    = (const float*)d_in[13];
  const float* b2    = (const float*)d_in[14];
  const float* ln2g  = (const float*)d_in[15];
  const float* ln2b  = (const float*)d_in[16];
  const float* hw    = (const float*)d_in[17];
  const float* hb    = (const float*)d_in[18];
  float* out = (float*)d_out;

  float *p_hbuf, *p_qkvc, *p_attno, *p_pp, *p_ffp, *p_y;
  __half *p_hwh;
  __nv_bfloat16 *p_wsh, *p_wsl;
  cudaGetSymbolAddress((void**)&p_hbuf,  g_hbuf);
  cudaGetSymbolAddress((void**)&p_qkvc,  g_qkvc);
  cudaGetSymbolAddress((void**)&p_attno, g_attno);
  cudaGetSymbolAddress((void**)&p_pp,    g_pp);
  cudaGetSymbolAddress((void**)&p_ffp,   g_ffp);
  cudaGetSymbolAddress((void**)&p_y,     g_y);
  cudaGetSymbolAddress((void**)&p_hwh,   g_hwh);
  cudaGetSymbolAddress((void**)&p_wsh,   g_wsh);
  cudaGetSymbolAddress((void**)&p_wsl,   g_wsl);

  const int SM_SML = (64+128)*256;
  cudaFuncSetAttribute(gemm_mma_kernel<64,128,1>,
                       cudaFuncAttributeMaxDynamicSharedMemorySize, SM_SML);
  cudaFuncSetAttribute(gemm_mma_kernel<64,128,2>,
                       cudaFuncAttributeMaxDynamicSharedMemorySize, SM_SML);
  cudaFuncSetAttribute(gemm_head_kernel,
                       cudaFuncAttributeMaxDynamicSharedMemorySize, HEAD_SMEM);
  cudaFuncSetAttribute(attn_kernel,
                       cudaFuncAttributeMaxDynamicSharedMemorySize, ATTN_SMEM);

  conv_w16_kernel<<<((int)((size_t)CC*DD/4) + 255)/256, 256>>>(hw, p_hwh, (int)((size_t)CC*DD/4));
  conv_w_kernel<<<(2304*768/4 + 255)/256, 256>>>(ipw, p_wsh + OFF_IPW, p_wsl + OFF_IPW, 2304*768/4);
  conv_w_kernel<<<(768*768/4 + 255)/256, 256>>>(aow, p_wsh + OFF_AOW, p_wsl + OFF_AOW, 768*768/4);
  conv_w_kernel<<<(768*768/4 + 255)/256, 256>>>(w1,  p_wsh + OFF_W1,  p_wsl + OFF_W1,  768*768/4);
  conv_w_kernel<<<(768*768/4 + 255)/256, 256>>>(w2,  p_wsh + OFF_W2,  p_wsl + OFF_W2,  768*768/4);

  embed_kernel<<<NROW, 256>>>(x, emb, pos, temb);

  dim3 grid_sk(NROW/64, DD/128, 2);
  dim3 grid_qkv(NROW/64, QKVLD/128);
  dim3 grid_attn(LL/32, HH, BB);

  for (int step = 0; step < NSTEPS; step++) {
    const float* slotA = p_hbuf + (size_t)step * DD;

    gemm_mma_kernel<64,128,1><<<grid_qkv, 128, SM_SML>>>(
        slotA, 7*DD, nullptr, p_wsh + OFF_IPW, p_wsl + OFF_IPW, ipb,
        p_qkvc + (size_t)step*QKVLD, 6*QKVLD, QKVLD, 0);

    attn_kernel<<<grid_attn, 256, ATTN_SMEM>>>(amask, step + 1);

    gemm_mma_kernel<64,128,2><<<grid_sk, 128, SM_SML>>>(
        p_attno, DD, nullptr, p_wsh + OFF_AOW, p_wsl + OFF_AOW, aob, p_pp, DD, DD, 0);
    add_ln_kernel<<<NROW, 256>>>(p_pp, p_pp + CSP, DD, slotA, 7*DD,
                                 ln1g, ln1b, p_y, DD, nullptr);

    gemm_mma_kernel<64,128,2><<<grid_sk, 128, SM_SML>>>(
        p_y, DD, nullptr, p_wsh + OFF_W1, p_wsl + OFF_W1, b1, p_ffp, DD, DD, 0);
    gemm_mma_kernel<64,128,2><<<grid_sk, 128, SM_SML>>>(
        p_ffp, DD, p_ffp + CSP, p_wsh + OFF_W2, p_wsl + OFF_W2, b2, p_pp, DD, DD, 0);
    const float* tv = (step + 1 < NSTEPS) ? temb + (size_t)(step+1)*DD : nullptr;
    add_ln_kernel<<<NROW, 256>>>(p_pp, p_pp + CSP, DD, p_y, DD, ln2g, ln2b,
                                 p_hbuf + (size_t)(step + 1) * DD, 7*DD, tv);
  }

  dim3 grid_head(NROW/128, (CC + 127)/128);
  gemm_head_kernel<<<grid_head, 256, HEAD_SMEM>>>(
      p_hbuf + (size_t)6*DD, 7*DD, p_hwh, hb, out);
}

// round 17
// speedup vs baseline: 1.0199x; 1.0199x over previous
#include <cuda_runtime.h>
#include <cuda_bf16.h>
#include <cuda_fp16.h>
#include <math.h>
#include <stdint.h>

#define BB 4
#define LL 256
#define DD 768
#define HH 12
#define NSTEPS 6
#define NROW 1024
#define CC 50257
#define QKVLD 2304
#define KDIM 768
#define CSP (NROW*DD)

#define OFF_IPW 0
#define OFF_AOW (2304*768)
#define OFF_W1  ((2304+768)*768)
#define OFF_W2  ((2304+2*768)*768)
#define WS_TOT  ((2304+3*768)*768)

// ---------------- scratch ----------------
__device__ float g_hbuf[(size_t)NROW*7*DD];
__device__ float g_qkvc[(size_t)NROW*6*QKVLD];
__device__ float g_attno[(size_t)NROW*DD];
__device__ float g_pp [(size_t)4*CSP];           // split-K=4 partials
__device__ float g_ffp[(size_t)4*CSP];
__device__ float g_y  [(size_t)NROW*DD];
__device__ __half g_hwh[(size_t)CC*DD];          // head W fp16
__device__ __nv_bfloat16 g_wsh[(size_t)WS_TOT];  // small weights hi
__device__ __nv_bfloat16 g_wsl[(size_t)WS_TOT];  // small weights lo

// ---------------- helpers ----------------
__device__ __forceinline__ uint32_t s2u(const void* p){
  uint32_t a; asm("{ .reg .u64 t; cvta.to.shared.u64 t, %1; cvt.u32.u64 %0, t; }"
                  : "=r"(a) : "l"(p)); return a;
}
__device__ __forceinline__ void ldsm4(uint32_t* r, uint32_t addr){
  asm volatile("ldmatrix.sync.aligned.m8n8.x4.shared.b16 {%0,%1,%2,%3}, [%4];"
    : "=r"(r[0]),"=r"(r[1]),"=r"(r[2]),"=r"(r[3]) : "r"(addr));
}
__device__ __forceinline__ void mma16816(float* c, const uint32_t* a, const uint32_t* b){
  asm volatile("mma.sync.aligned.m16n8k16.row.col.f32.bf16.bf16.f32 "
    "{%0,%1,%2,%3}, {%4,%5,%6,%7}, {%8,%9}, {%0,%1,%2,%3};"
    : "+f"(c[0]),"+f"(c[1]),"+f"(c[2]),"+f"(c[3])
    : "r"(a[0]),"r"(a[1]),"r"(a[2]),"r"(a[3]), "r"(b[0]),"r"(b[1]));
}
__device__ __forceinline__ void mma16816h(float* c, const uint32_t* a, const uint32_t* b){
  asm volatile("mma.sync.aligned.m16n8k16.row.col.f32.f16.f16.f32 "
    "{%0,%1,%2,%3}, {%4,%5,%6,%7}, {%8,%9}, {%0,%1,%2,%3};"
    : "+f"(c[0]),"+f"(c[1]),"+f"(c[2]),"+f"(c[3])
    : "r"(a[0]),"r"(a[1]),"r"(a[2]),"r"(a[3]), "r"(b[0]),"r"(b[1]));
}
__device__ __forceinline__ void split2(float a, float b, uint32_t& h, uint32_t& l){
  __nv_bfloat16 ha = __float2bfloat16(a), hb = __float2bfloat16(b);
  __nv_bfloat16 la = __float2bfloat16(a - __bfloat162float(ha));
  __nv_bfloat16 lb = __float2bfloat16(b - __bfloat162float(hb));
  uint16_t uha = *(uint16_t*)&ha, uhb = *(uint16_t*)&hb;
  uint16_t ula = *(uint16_t*)&la, ulb = *(uint16_t*)&lb;
  h = ((uint32_t)uhb << 16) | uha;
  l = ((uint32_t)ulb << 16) | ula;
}

// ---------------- weight conversions ----------------
__global__ void conv_w_kernel(const float* __restrict__ w,
                              __nv_bfloat16* __restrict__ h,
                              __nv_bfloat16* __restrict__ l, int n4)
{
  int i = blockIdx.x * 256 + threadIdx.x;
  if (i >= n4) return;
  float4 v = reinterpret_cast<const float4*>(w)[i];
  uint32_t h0,l0,h1,l1;
  split2(v.x, v.y, h0, l0);
  split2(v.z, v.w, h1, l1);
  *(uint2*)(h + (size_t)i*4) = make_uint2(h0, h1);
  *(uint2*)(l + (size_t)i*4) = make_uint2(l0, l1);
}
__global__ void conv_w16_kernel(const float* __restrict__ w,
                                __half* __restrict__ h, int n4)
{
  int i = blockIdx.x * 256 + threadIdx.x;
  if (i >= n4) return;
  float4 v = reinterpret_cast<const float4*>(w)[i];
  __half2 a = __floats2half2_rn(v.x, v.y);
  __half2 b = __floats2half2_rn(v.z, v.w);
  *(uint2*)(h + (size_t)i*4) = make_uint2(*(uint32_t*)&a, *(uint32_t*)&b);
}

// ---------------- elementwise ----------------
__global__ void embed_kernel(const int* __restrict__ x, const float* __restrict__ emb,
                             const float* __restrict__ pos, const float* __restrict__ te0) {
  int n = blockIdx.x;
  int l = n % LL;
  int tok = x[n];
  const float* e = emb + (size_t)tok * DD;
  const float* p = pos + (size_t)l * DD;
  float* dst = g_hbuf + (size_t)n * 7 * DD;
  for (int i = threadIdx.x; i < DD; i += blockDim.x) dst[i] = e[i] + p[i] + te0[i];
}

// ---------------- bf16 3-term GEMM (pre-split W), split-K + multi-partial A --
// If APART>1: effective A = relu(sum_{z<APART} A[z*CSP]).
template<int BM, int BN, int SPLITK, int APART>
__global__ __launch_bounds__((BM/64)*(BN/32)*32)
void gemm_mma_kernel(const float* __restrict__ A, int lda,
                     const __nv_bfloat16* __restrict__ Wh,
                     const __nv_bfloat16* __restrict__ Wl,
                     const float* __restrict__ bias,
                     float* __restrict__ C, int ldc,
                     int N, int relu)
{
  constexpr int NWN = BN/32;
  constexpr int NTHR = (BM/64)*(BN/32)*32;
  constexpr int RPP = NTHR/8;
  constexpr int PA = BM/RPP, PB = BN/RPP;
  constexpr int ABYTES = BM*64, BBYTES = BN*64;
  constexpr int NIT = KDIM/32/SPLITK;

  extern __shared__ char smem[];
  const int OAh = 0, OAl = 2*ABYTES, OBh = 4*ABYTES, OBl = 4*ABYTES + 2*BBYTES;
  uint32_t sb = s2u(smem);

  int tid = threadIdx.x, lane = tid & 31, wid = tid >> 5;
  int wm = wid / NWN, wn = wid % NWN;
  int bm = blockIdx.x * BM, bn = blockIdx.y * BN;
  int kz = (SPLITK > 1) ? blockIdx.z : 0;
  int kbase = kz * (KDIM / SPLITK);
  int lr = tid >> 3, lq = tid & 7;

  float acc[4][4][4];
  #pragma unroll
  for (int i = 0; i < 4; i++)
    #pragma unroll
    for (int j = 0; j < 4; j++)
      #pragma unroll
      for (int q = 0; q < 4; q++) acc[i][j][q] = 0.f;

  float4 sa[PA];
  uint2 wh_[PB], wl_[PB];

  auto load_tiles = [&](int k0){
    #pragma unroll
    for (int p = 0; p < PA; p++) {
      size_t off = (size_t)(bm + p*RPP + lr) * lda + kbase + k0 + lq*4;
      sa[p] = *(const float4*)(A + off);
      if (APART > 1) {
        #pragma unroll
        for (int z = 1; z < APART; z++) {
          float4 b2 = *(const float4*)(A + off + (size_t)z*CSP);
          sa[p].x += b2.x; sa[p].y += b2.y; sa[p].z += b2.z; sa[p].w += b2.w;
        }
        sa[p].x = fmaxf(sa[p].x, 0.f); sa[p].y = fmaxf(sa[p].y, 0.f);
        sa[p].z = fmaxf(sa[p].z, 0.f); sa[p].w = fmaxf(sa[p].w, 0.f);
      }
    }
    #pragma unroll
    for (int p = 0; p < PB; p++) {
      int wr = bn + p*RPP + lr;
      size_t off = (size_t)wr * KDIM + kbase + k0 + lq*4;
      wh_[p] = *(const uint2*)(Wh + off);
      wl_[p] = *(const uint2*)(Wl + off);
    }
  };
  auto store_tiles = [&](int b){
    #pragma unroll
    for (int p = 0; p < PA; p++) {
      int r = p*RPP + lr;
      int byte = r*64 + ((((lq>>1) ^ ((r>>1)&3))<<4) | ((lq&1)<<3));
      uint32_t h0,l0,h1,l1;
      split2(sa[p].x, sa[p].y, h0, l0);
      split2(sa[p].z, sa[p].w, h1, l1);
      *(uint2*)(smem + OAh + b*ABYTES + byte) = make_uint2(h0,h1);
      *(uint2*)(smem + OAl + b*ABYTES + byte) = make_uint2(l0,l1);
    }
    #pragma unroll
    for (int p = 0; p < PB; p++) {
      int r = p*RPP + lr;
      int byte = r*64 + ((((lq>>1) ^ ((r>>1)&3))<<4) | ((lq&1)<<3));
      *(uint2*)(smem + OBh + b*BBYTES + byte) = wh_[p];
      *(uint2*)(smem + OBl + b*BBYTES + byte) = wl_[p];
    }
  };

  load_tiles(0);
  store_tiles(0);
  __syncthreads();

  int buf = 0;
  for (int it = 0; it < NIT; it++) {
    bool more = (it < NIT-1);
    if (more) load_tiles((it+1)*32);

    #pragma unroll
    for (int ks = 0; ks < 2; ks++) {
      uint32_t ah[4][4], al[4][4], bh[4][2], bl[4][2];
      #pragma unroll
      for (int mi = 0; mi < 4; mi++) {
        int r = wm*64 + mi*16 + (lane & 15);
        int kc = ks*2 + (lane >> 4);
        uint32_t byte = r*64 + ((kc ^ ((r>>1)&3))<<4);
        ldsm4(ah[mi], sb + OAh + buf*ABYTES + byte);
        ldsm4(al[mi], sb + OAl + buf*ABYTES + byte);
      }
      #pragma unroll
      for (int np = 0; np < 2; np++) {
        int r = wn*32 + np*16 + (lane & 7) + ((lane>>4)&1)*8;
        int kc = ks*2 + ((lane>>3)&1);
        uint32_t byte = r*64 + ((kc ^ ((r>>1)&3))<<4);
        uint32_t t4[4];
        ldsm4(t4, sb + OBh + buf*BBYTES + byte);
        bh[np*2][0]=t4[0]; bh[np*2][1]=t4[1]; bh[np*2+1][0]=t4[2]; bh[np*2+1][1]=t4[3];
        ldsm4(t4, sb + OBl + buf*BBYTES + byte);
        bl[np*2][0]=t4[0]; bl[np*2][1]=t4[1]; bl[np*2+1][0]=t4[2]; bl[np*2+1][1]=t4[3];
      }
      #pragma unroll
      for (int mi = 0; mi < 4; mi++)
        #pragma unroll
        for (int ni = 0; ni < 4; ni++) {
          mma16816(acc[mi][ni], ah[mi], bh[ni]);
          mma16816(acc[mi][ni], ah[mi], bl[ni]);
          mma16816(acc[mi][ni], al[mi], bh[ni]);
        }
    }
    if (more) {
      store_tiles(buf ^ 1);
      __syncthreads();
      buf ^= 1;
    }
  }

  float* Cz = C + (size_t)kz * CSP;
  bool addb = (kz == 0);
  #pragma unroll
  for (int mi = 0; mi < 4; mi++) {
    int r0 = bm + wm*64 + mi*16 + (lane >> 2);
    #pragma unroll
    for (int ni = 0; ni < 4; ni++) {
      int c0 = bn + wn*32 + ni*8 + ((lane & 3) << 1);
      float* p0 = Cz + (size_t)r0 * ldc;
      float* p1 = Cz + (size_t)(r0 + 8) * ldc;
      float bv0 = addb ? __ldg(bias + c0) : 0.f;
      float bv1 = addb ? __ldg(bias + c0 + 1) : 0.f;
      float v0 = acc[mi][ni][0] + bv0, v1 = acc[mi][ni][1] + bv1;
      float v2 = acc[mi][ni][2] + bv0, v3 = acc[mi][ni][3] + bv1;
      if (relu) {
        v0 = fmaxf(v0, 0.f); v1 = fmaxf(v1, 0.f);
        v2 = fmaxf(v2, 0.f); v3 = fmaxf(v3, 0.f);
      }
      p0[c0] = v0; p0[c0+1] = v1; p1[c0] = v2; p1[c0+1] = v3;
    }
  }
}

// ---------------- fp16 1-term head GEMM ----------------
#define HEAD_SMEM (4*128*64)
__global__ __launch_bounds__(256)
void gemm_head_kernel(const float* __restrict__ A, int lda,
                      const __half* __restrict__ Wh,
                      const float* __restrict__ bias,
                      float* __restrict__ C)
{
  constexpr int BM = 128, BN = 128;
  constexpr int ABYTES = BM*64, BBYTES = BN*64;
  constexpr int NIT = KDIM/32;

  extern __shared__ char smem[];
  const int OAh = 0, OBh = 2*ABYTES;
  uint32_t sb = s2u(smem);

  int tid = threadIdx.x, lane = tid & 31, wid = tid >> 5;
  int wm = wid >> 2, wn = wid & 3;
  int bm = blockIdx.x * BM, bn = blockIdx.y * BN;
  int lr = tid >> 3, lq = tid & 7;

  float acc[4][4][4];
  #pragma unroll
  for (int i = 0; i < 4; i++)
    #pragma unroll
    for (int j = 0; j < 4; j++)
      #pragma unroll
      for (int q = 0; q < 4; q++) acc[i][j][q] = 0.f;

  float4 sa[4];
  uint2 wv[4];

  auto load_tiles = [&](int k0){
    #pragma unroll
    for (int p = 0; p < 4; p++)
      sa[p] = *(const float4*)(A + (size_t)(bm + p*32 + lr) * lda + k0 + lq*4);
    #pragma unroll
    for (int p = 0; p < 4; p++) {
      int wr = bn + p*32 + lr;
      wv[p] = (wr < CC) ? *(const uint2*)(Wh + (size_t)wr * KDIM + k0 + lq*4)
                        : make_uint2(0,0);
    }
  };
  auto store_tiles = [&](int b){
    #pragma unroll
    for (int p = 0; p < 4; p++) {
      int r = p*32 + lr;
      int byte = r*64 + ((((lq>>1) ^ ((r>>1)&3))<<4) | ((lq&1)<<3));
      __half2 h0 = __floats2half2_rn(sa[p].x, sa[p].y);
      __half2 h1 = __floats2half2_rn(sa[p].z, sa[p].w);
      *(uint2*)(smem + OAh + b*ABYTES + byte) =
          make_uint2(*(uint32_t*)&h0, *(uint32_t*)&h1);
    }
    #pragma unroll
    for (int p = 0; p < 4; p++) {
      int r = p*32 + lr;
      int byte = r*64 + ((((lq>>1) ^ ((r>>1)&3))<<4) | ((lq&1)<<3));
      *(uint2*)(smem + OBh + b*BBYTES + byte) = wv[p];
    }
  };

  load_tiles(0);
  store_tiles(0);
  __syncthreads();

  int buf = 0;
  for (int it = 0; it < NIT; it++) {
    bool more = (it < NIT-1);
    if (more) load_tiles((it+1)*32);

    #pragma unroll
    for (int ks = 0; ks < 2; ks++) {
      uint32_t ah[4][4], bh[4][2];
      #pragma unroll
      for (int mi = 0; mi < 4; mi++) {
        int r = wm*64 + mi*16 + (lane & 15);
        int kc = ks*2 + (lane >> 4);
        uint32_t byte = r*64 + ((kc ^ ((r>>1)&3))<<4);
        ldsm4(ah[mi], sb + OAh + buf*ABYTES + byte);
      }
      #pragma unroll
      for (int np = 0; np < 2; np++) {
        int r = wn*32 + np*16 + (lane & 7) + ((lane>>4)&1)*8;
        int kc = ks*2 + ((lane>>3)&1);
        uint32_t byte = r*64 + ((kc ^ ((r>>1)&3))<<4);
        uint32_t t4[4];
        ldsm4(t4, sb + OBh + buf*BBYTES + byte);
        bh[np*2][0]=t4[0]; bh[np*2][1]=t4[1]; bh[np*2+1][0]=t4[2]; bh[np*2+1][1]=t4[3];
      }
      #pragma unroll
      for (int mi = 0; mi < 4; mi++)
        #pragma unroll
        for (int ni = 0; ni < 4; ni++)
          mma16816h(acc[mi][ni], ah[mi], bh[ni]);
    }
    if (more) {
      store_tiles(buf ^ 1);
      __syncthreads();
      buf ^= 1;
    }
  }

  #pragma unroll
  for (int mi = 0; mi < 4; mi++) {
    int r0 = bm + wm*64 + mi*16 + (lane >> 2);
    #pragma unroll
    for (int ni = 0; ni < 4; ni++) {
      int c0 = bn + wn*32 + ni*8 + ((lane & 3) << 1);
      float* p0 = C + (size_t)r0 * CC;
      float* p1 = C + (size_t)(r0 + 8) * CC;
      if (c0 < CC) {
        float bv = __ldg(bias + c0);
        p0[c0] = acc[mi][ni][0] + bv;
        p1[c0] = acc[mi][ni][2] + bv;
      }
      if (c0 + 1 < CC) {
        float bv = __ldg(bias + c0 + 1);
        p0[c0+1] = acc[mi][ni][1] + bv;
        p1[c0+1] = acc[mi][ni][3] + bv;
      }
    }
  }
}

// ---------------- flash attention (R15 known-good) ----------------
#define ATTN_SMEM ((64*36 + 64*132 + 32*132)*4 + 256*4)
__global__ __launch_bounds__(256) void attn_kernel(const int* __restrict__ amask, int t)
{
  int qt = blockIdx.x, h = blockIdx.y, b = blockIdx.z;
  int tid = threadIdx.x, lane = tid & 31, w = tid >> 5;
  extern __shared__ float sm[];
  float* Qs = sm;
  float* Kt = Qs + 64*36;
  float* P  = Kt + 64*132;
  int*   mkk = (int*)(P + 32*132);

  int l0 = qt * 32;
  size_t cbase = (size_t)b * LL * 6 * QKVLD;

  if (tid < 256) mkk[tid] = amask[b*LL + tid];
  {
    int q = tid >> 3, e0 = (tid & 7) * 8;
    const float* qp = g_qkvc + ((size_t)((b*LL + l0 + q)*6 + (t-1)))*QKVLD + h*64 + e0;
    #pragma unroll
    for (int i = 0; i < 8; i++) Qs[(e0+i)*36 + q] = qp[i];
  }

  float m[4], lsum[4], oacc[4][2];
  #pragma unroll
  for (int i = 0; i < 4; i++) {
    m[i] = -1e30f; lsum[i] = 0.f; oacc[i][0] = 0.f; oacc[i][1] = 0.f;
  }

  #pragma unroll
  for (int kt = 0; kt < 2; kt++) {
    __syncthreads();
    {
      int k = tid >> 1, e0 = (tid & 1) * 32;
      const float* kp = g_qkvc + cbase + (size_t)(kt*128 + k)*6*QKVLD + DD + h*64 + e0;
      #pragma unroll
      for (int i = 0; i < 32; i++) Kt[(e0+i)*132 + k] = kp[i];
    }
    __syncthreads();

    float s[4][4];
    #pragma unroll
    for (int i = 0; i < 4; i++)
      #pragma unroll
      for (int j = 0; j < 4; j++) s[i][j] = 0.f;
    #pragma unroll 8
    for (int e = 0; e < 64; e++) {
      float4 qv = *(const float4*)&Qs[e*36 + w*4];
      float4 kv = *(const float4*)&Kt[e*132 + lane*4];
      s[0][0]+=qv.x*kv.x; s[0][1]+=qv.x*kv.y; s[0][2]+=qv.x*kv.z; s[0][3]+=qv.x*kv.w;
      s[1][0]+=qv.y*kv.x; s[1][1]+=qv.y*kv.y; s[1][2]+=qv.y*kv.z; s[1][3]+=qv.y*kv.w;
      s[2][0]+=qv.z*kv.x; s[2][1]+=qv.z*kv.y; s[2][2]+=qv.z*kv.z; s[2][3]+=qv.z*kv.w;
      s[3][0]+=qv.w*kv.x; s[3][1]+=qv.w*kv.y; s[3][2]+=qv.w*kv.z; s[3][3]+=qv.w*kv.w;
    }
    int j0 = kt*128 + lane*4;
    float msk[4];
    #pragma unroll
    for (int j = 0; j < 4; j++) msk[j] = mkk[j0+j] ? 0.f : -1e30f;
    #pragma unroll
    for (int i = 0; i < 4; i++) {
      #pragma unroll
      for (int j = 0; j < 4; j++) s[i][j] = s[i][j]*0.125f + msk[j];
      float mt = fmaxf(fmaxf(s[i][0], s[i][1]), fmaxf(s[i][2], s[i][3]));
      #pragma unroll
      for (int o = 16; o; o >>= 1) mt = fmaxf(mt, __shfl_xor_sync(0xffffffffu, mt, o));
      float mnew = fmaxf(m[i], mt);
      float ps = 0.f;
      #pragma unroll
      for (int j = 0; j < 4; j++) { s[i][j] = __expf(s[i][j] - mnew); ps += s[i][j]; }
      #pragma unroll
      for (int o = 16; o; o >>= 1) ps += __shfl_xor_sync(0xffffffffu, ps, o);
      float alpha = __expf(m[i] - mnew);
      lsum[i] = lsum[i]*alpha + ps;
      oacc[i][0] *= alpha; oacc[i][1] *= alpha;
      m[i] = mnew;
    }
    #pragma unroll
    for (int i = 0; i < 4; i++)
      *(float4*)&P[(w*4 + i)*132 + lane*4] = make_float4(s[i][0], s[i][1], s[i][2], s[i][3]);
    __syncwarp();

    #pragma unroll 4
    for (int k = 0; k < 128; k++) {
      const float2 v = *(const float2*)(g_qkvc + cbase + (size_t)(kt*128 + k)*6*QKVLD
                                        + 2*DD + h*64 + lane*2);
      float p0 = P[(w*4+0)*132 + k];
      float p1 = P[(w*4+1)*132 + k];
      float p2 = P[(w*4+2)*132 + k];
      float p3 = P[(w*4+3)*132 + k];
      oacc[0][0] += p0*v.x; oacc[0][1] += p0*v.y;
      oacc[1][0] += p1*v.x; oacc[1][1] += p1*v.y;
      oacc[2][0] += p2*v.x; oacc[2][1] += p2*v.y;
      oacc[3][0] += p3*v.x; oacc[3][1] += p3*v.y;
    }
  }

  for (int s = 1; s < t; s++) {
    #pragma unroll
    for (int i = 0; i < 4; i++) {
      int qloc = w*4 + i;
      int row = b*LL + l0 + qloc;
      const float* base = g_qkvc + ((size_t)(row*6 + s))*QKVLD;
      float2 kv = *(const float2*)(base + DD + h*64 + lane*2);
      float d = Qs[(2*lane)*36 + qloc]*kv.x + Qs[(2*lane+1)*36 + qloc]*kv.y;
      #pragma unroll
      for (int o = 16; o; o >>= 1) d += __shfl_xor_sync(0xffffffffu, d, o);
      d = (amask[row] != 0) ? d*0.125f : -1e30f;
      float mnew = fmaxf(m[i], d);
      float p = __expf(d - mnew);
      float alpha = __expf(m[i] - mnew);
      lsum[i] = lsum[i]*alpha + p;
      float2 v = *(const float2*)(base + 2*DD + h*64 + lane*2);
      oacc[i][0] = oacc[i][0]*alpha + p*v.x;
      oacc[i][1] = oacc[i][1]*alpha + p*v.y;
      m[i] = mnew;
    }
  }

  #pragma unroll
  for (int i = 0; i < 4; i++) {
    int qloc = w*4 + i;
    int row = b*LL + l0 + qloc;
    float iv = 1.f / lsum[i];
    *(float2*)(g_attno + (size_t)row*DD + h*64 + lane*2) =
        make_float2(oacc[i][0]*iv, oacc[i][1]*iv);
  }
}

// ---------------- fused (4 partials)+residual + LayerNorm (+time emb) --------
__global__ void add_ln_kernel(const float* __restrict__ A, int nparts, int lda,
                              const float* __restrict__ R, int ldr,
                              const float* __restrict__ gma, const float* __restrict__ bta,
                              float* __restrict__ out, int ldo,
                              const float* __restrict__ tvec)
{
  int row = blockIdx.x;
  int tid = threadIdx.x;
  const float* pa = A + (size_t)row * lda;
  const float* pr = R + (size_t)row * ldr;
  float* po = out + (size_t)row * ldo;
  float v[3]; float s = 0.f, sq = 0.f;
  #pragma unroll
  for (int i = 0; i < 3; i++) {
    int idx = tid + i * 256;
    float xx = pr[idx];
    for (int z = 0; z < nparts; z++) xx += pa[idx + (size_t)z*CSP];
    v[i] = xx; s += xx; sq += xx * xx;
  }
  __shared__ float r1[8], r2[8];
  for (int o = 16; o; o >>= 1) {
    s  += __shfl_xor_sync(0xffffffffu, s, o);
    sq += __shfl_xor_sync(0xffffffffu, sq, o);
  }
  if ((tid & 31) == 0) { r1[tid >> 5] = s; r2[tid >> 5] = sq; }
  __syncthreads();
  s = 0.f; sq = 0.f;
  #pragma unroll
  for (int ww = 0; ww < 8; ww++) { s += r1[ww]; sq += r2[ww]; }
  float mean = s * (1.f / DD);
  float var  = sq * (1.f / DD) - mean * mean;
  float rinv = rsqrtf(var + 1e-5f);
  #pragma unroll
  for (int i = 0; i < 3; i++) {
    int idx = tid + i * 256;
    float o = (v[i] - mean) * rinv * gma[idx] + bta[idx];
    if (tvec) o += tvec[idx];
    po[idx] = o;
  }
}

// ---------------- host launch ----------------
extern "C" void kernel_launch(void* const* d_in, const int* in_sizes, int n_in,
                              void* d_out, int out_size)
{
  const int*   x     = (const int*)d_in[0];
  const int*   amask = (const int*)d_in[1];
  const float* emb   = (const float*)d_in[2];
  const float* pos   = (const float*)d_in[3];
  const float* temb  = (const float*)d_in[4];
  const float* ipw   = (const float*)d_in[5];
  const float* ipb   = (const float*)d_in[6];
  const float* aow   = (const float*)d_in[7];
  const float* aob   = (const float*)d_in[8];
  const float* ln1g  = (const float*)d_in[9];
  const float* ln1b  = (const float*)d_in[10];
  const float* w1    = (const float*)d_in[11];
  const float* b1    = (const float*)d_in[12];
  const float* w2    = (const float*)d_in[13];
  const float* b2    = (const float*)d_in[14];
  const float* ln2g  = (const float*)d_in[15];
  const float* ln2b  = (const float*)d_in[16];
  const float* hw    = (const float*)d_in[17];
  const float* hb    = (const float*)d_in[18];
  float* out = (float*)d_out;

  float *p_hbuf, *p_qkvc, *p_attno, *p_pp, *p_ffp, *p_y;
  __half *p_hwh;
  __nv_bfloat16 *p_wsh, *p_wsl;
  cudaGetSymbolAddress((void**)&p_hbuf,  g_hbuf);
  cudaGetSymbolAddress((void**)&p_qkvc,  g_qkvc);
  cudaGetSymbolAddress((void**)&p_attno, g_attno);
  cudaGetSymbolAddress((void**)&p_pp,    g_pp);
  cudaGetSymbolAddress((void**)&p_ffp,   g_ffp);
  cudaGetSymbolAddress((void**)&p_y,     g_y);
  cudaGetSymbolAddress((void**)&p_hwh,   g_hwh);
  cudaGetSymbolAddress((void**)&p_wsh,   g_wsh);
  cudaGetSymbolAddress((void**)&p_wsl,   g_wsl);

  const int SM_SML = (64+128)*256;
  cudaFuncSetAttribute(gemm_mma_kernel<64,128,1,1>,
                       cudaFuncAttributeMaxDynamicSharedMemorySize, SM_SML);
  cudaFuncSetAttribute(gemm_mma_kernel<64,128,4,1>,
                       cudaFuncAttributeMaxDynamicSharedMemorySize, SM_SML);
  cudaFuncSetAttribute(gemm_mma_kernel<64,128,4,4>,
                       cudaFuncAttributeMaxDynamicSharedMemorySize, SM_SML);
  cudaFuncSetAttribute(gemm_head_kernel,
                       cudaFuncAttributeMaxDynamicSharedMemorySize, HEAD_SMEM);
  cudaFuncSetAttribute(attn_kernel,
                       cudaFuncAttributeMaxDynamicSharedMemorySize, ATTN_SMEM);

  conv_w16_kernel<<<((int)((size_t)CC*DD/4) + 255)/256, 256>>>(hw, p_hwh, (int)((size_t)CC*DD/4));
  conv_w_kernel<<<(2304*768/4 + 255)/256, 256>>>(ipw, p_wsh + OFF_IPW, p_wsl + OFF_IPW, 2304*768/4);
  conv_w_kernel<<<(768*768/4 + 255)/256, 256>>>(aow, p_wsh + OFF_AOW, p_wsl + OFF_AOW, 768*768/4);
  conv_w_kernel<<<(768*768/4 + 255)/256, 256>>>(w1,  p_wsh + OFF_W1,  p_wsl + OFF_W1,  768*768/4);
  conv_w_kernel<<<(768*768/4 + 255)/256, 256>>>(w2,  p_wsh + OFF_W2,  p_wsl + OFF_W2,  768*768/4);

  embed_kernel<<<NROW, 256>>>(x, emb, pos, temb);

  dim3 grid_sk(NROW/64, DD/128, 4);    // split-K=4: 384 blocks
  dim3 grid_qkv(NROW/64, QKVLD/128);
  dim3 grid_attn(LL/32, HH, BB);

  for (int step = 0; step < NSTEPS; step++) {
    const float* slotA = p_hbuf + (size_t)step * DD;

    gemm_mma_kernel<64,128,1,1><<<grid_qkv, 128, SM_SML>>>(
        slotA, 7*DD, p_wsh + OFF_IPW, p_wsl + OFF_IPW, ipb,
        p_qkvc + (size_t)step*QKVLD, 6*QKVLD, QKVLD, 0);

    attn_kernel<<<grid_attn, 256, ATTN_SMEM>>>(amask, step + 1);

    gemm_mma_kernel<64,128,4,1><<<grid_sk, 128, SM_SML>>>(
        p_attno, DD, p_wsh + OFF_AOW, p_wsl + OFF_AOW, aob, p_pp, DD, DD, 0);
    add_ln_kernel<<<NROW, 256>>>(p_pp, 4, DD, slotA, 7*DD,
                                 ln1g, ln1b, p_y, DD, nullptr);

    gemm_mma_kernel<64,128,4,1><<<grid_sk, 128, SM_SML>>>(
        p_y, DD, p_wsh + OFF_W1, p_wsl + OFF_W1, b1, p_ffp, DD, DD, 0);
    gemm_mma_kernel<64,128,4,4><<<grid_sk, 128, SM_SML>>>(
        p_ffp, DD, p_wsh + OFF_W2, p_wsl + OFF_W2, b2, p_pp, DD, DD, 0);
    const float* tv = (step + 1 < NSTEPS) ? temb + (size_t)(step+1)*DD : nullptr;
    add_ln_kernel<<<NROW, 256>>>(p_pp, 4, DD, p_y, DD, ln2g, ln2b,
                                 p_hbuf + (size_t)(step + 1) * DD, 7*DD, tv);
  }

  dim3 grid_head(NROW/128, (CC + 127)/128);
  gemm_head_kernel<<<grid_head, 256, HEAD_SMEM>>>(
      p_hbuf + (size_t)6*DD, 7*DD, p_hwh, hb, out);
}